// round 2
// baseline (speedup 1.0000x reference)
#include <cuda_runtime.h>
#include <cuda_bf16.h>

// Problem constants
#define Bz 16
#define Nn 5000
#define Ff 64
#define Hh 32
#define Ee 160000
#define ETOT (Ee + Nn)         // edges + self loops = 165000
#define Kdim (Nn * Hh)         // 160000
#define NHID 512
#define NACT 16
#define KSPLIT 296

// -------- scratch (device globals; no allocation allowed) --------
__device__ int   g_is64;
__device__ int   g_deg[Nn];
__device__ int   g_cursor[Nn];
__device__ int   g_off[Nn + 1];
__device__ float g_dinv[Nn];
__device__ int   g_srcs[ETOT];
__device__ float g_nrms[ETOT];
__device__ float g_bufA[Bz * Nn * Hh];   // 10.24 MB
__device__ float g_bufB[Bz * Nn * Hh];   // 10.24 MB
__device__ float g_hid[Bz * NHID];       // partial sums for MLP layer 1

// edge index fetch that works for both int32 and int64 payloads
__device__ __forceinline__ int edge_at(const void* ei, int idx) {
    if (g_is64) return (int)((const long long*)ei)[idx];
    return ((const int*)ei)[idx];
}

// ================= setup kernels =================

// Detect whether edge buffer holds int64 (odd 32-bit words all zero) or int32.
__global__ void detect_k(const unsigned int* __restrict__ ei) {
    if (threadIdx.x == 0) {
        int all0 = 1;
        for (int i = 0; i < 64; i++)
            if (ei[2 * i + 1] != 0u) { all0 = 0; break; }
        g_is64 = all0;
    }
}

__global__ void init_k() {
    int i = blockIdx.x * blockDim.x + threadIdx.x;
    if (i < Nn) { g_deg[i] = 1; g_cursor[i] = 0; }   // deg starts at 1 (self loop)
    if (i < Bz * NHID) g_hid[i] = 0.0f;
}

__global__ void hist_k(const void* __restrict__ ei) {
    int e = blockIdx.x * blockDim.x + threadIdx.x;
    if (e < Ee) {
        int d = edge_at(ei, Ee + e);
        atomicAdd(&g_deg[d], 1);
    }
}

// single block: dinv + exclusive scan of degrees
__global__ void scan_k() {
    __shared__ int ssum[1024];
    int t = threadIdx.x;
    const int CH = 5;                       // 1024*5 >= 5000
    int base = t * CH;
    int d[CH];
    int local = 0;
#pragma unroll
    for (int j = 0; j < CH; j++) {
        int idx = base + j;
        d[j] = (idx < Nn) ? g_deg[idx] : 0;
        local += d[j];
    }
    ssum[t] = local;
    __syncthreads();
    for (int off = 1; off < 1024; off <<= 1) {
        int v = (t >= off) ? ssum[t - off] : 0;
        __syncthreads();
        ssum[t] += v;
        __syncthreads();
    }
    int excl = ssum[t] - local;
#pragma unroll
    for (int j = 0; j < CH; j++) {
        int idx = base + j;
        if (idx < Nn) {
            g_off[idx] = excl;
            excl += d[j];
            g_dinv[idx] = rsqrtf((float)d[j]);   // deg >= 1 always
        }
    }
    if (t == 1023) g_off[Nn] = ssum[1023];
}

__global__ void scatter_k(const void* __restrict__ ei) {
    int i = blockIdx.x * blockDim.x + threadIdx.x;
    if (i >= ETOT) return;
    int s, d;
    if (i < Ee) { s = edge_at(ei, i); d = edge_at(ei, Ee + i); }
    else        { s = d = i - Ee; }
    float nm = g_dinv[s] * g_dinv[d];
    int pos = g_off[d] + atomicAdd(&g_cursor[d], 1);
    g_srcs[pos] = s;
    g_nrms[pos] = nm;
}

// ================= node-feature GEMM: Y[r,32] = X[r,F] @ W[F,32] =================
// block = 256 threads, handles 64 rows. R = Bz*Nn = 80000 (divisible by 64).
__global__ __launch_bounds__(256) void gemm_rows_k(
    const float* __restrict__ X, const float* __restrict__ W,
    float* __restrict__ Y, int F)
{
    __shared__ float sx[64 * 64];
    __shared__ float sw[64 * 32];
    int tid = threadIdx.x;
    for (int i = tid; i < F * 32; i += 256) sw[i] = W[i];
    long long r0 = (long long)blockIdx.x * 64;
    for (int i = tid; i < 64 * F; i += 256) {
        int r = i / F, c = i - r * F;
        sx[r * F + c] = X[(r0 + r) * F + c];
    }
    __syncthreads();
    int h = tid & 31;
    int g = tid >> 5;               // 8 groups x 8 rows
    float acc[8] = {0.f, 0.f, 0.f, 0.f, 0.f, 0.f, 0.f, 0.f};
    for (int f = 0; f < F; f++) {
        float w = sw[f * 32 + h];
#pragma unroll
        for (int i = 0; i < 8; i++)
            acc[i] = fmaf(sx[(g * 8 + i) * F + f], w, acc[i]);
    }
#pragma unroll
    for (int i = 0; i < 8; i++)
        Y[(r0 + g * 8 + i) * 32 + h] = acc[i];
}

// ================= aggregation (gather form, no float atomics) =================
// block = 512 threads = 16 warps; warp w handles batch b=w for node n=blockIdx.x
__global__ __launch_bounds__(512) void agg_k(
    const float* __restrict__ xw, const float* __restrict__ bias,
    float* __restrict__ out)
{
    int n = blockIdx.x;
    int b = threadIdx.x >> 5;
    int lane = threadIdx.x & 31;
    int beg = g_off[n], end = g_off[n + 1];
    const float* xb = xw + (size_t)b * Nn * Hh;
    float a0 = 0.f, a1 = 0.f, a2 = 0.f, a3 = 0.f;
    int e = beg;
    for (; e + 4 <= end; e += 4) {
        int s0 = g_srcs[e], s1 = g_srcs[e + 1], s2 = g_srcs[e + 2], s3 = g_srcs[e + 3];
        float m0 = g_nrms[e], m1 = g_nrms[e + 1], m2 = g_nrms[e + 2], m3 = g_nrms[e + 3];
        a0 = fmaf(m0, xb[s0 * 32 + lane], a0);
        a1 = fmaf(m1, xb[s1 * 32 + lane], a1);
        a2 = fmaf(m2, xb[s2 * 32 + lane], a2);
        a3 = fmaf(m3, xb[s3 * 32 + lane], a3);
    }
    for (; e < end; e++) {
        int s = g_srcs[e];
        a0 = fmaf(g_nrms[e], xb[s * 32 + lane], a0);
    }
    float r = (a0 + a1) + (a2 + a3) + bias[lane];
    out[((size_t)b * Nn + n) * 32 + lane] = fmaxf(r, 0.0f);
}

// ================= big MLP GEMM: split-K, f32x2 packed batch pairs =================
// hid[b,j] += sum_k flat[b,k] * Wp1[k,j];  256 threads, thread owns cols 2t,2t+1
__global__ __launch_bounds__(256) void mlp1_k(
    const float* __restrict__ flat, const float* __restrict__ Wp1)
{
    __shared__ __align__(16) float sf[128][18];   // [k-within-tile][batch], padded
    int tid = threadIdx.x;
    const int chunk = (Kdim + KSPLIT - 1) / KSPLIT;   // 541
    int k0 = blockIdx.x * chunk;
    int k1 = min(k0 + chunk, Kdim);

    unsigned long long acc0[8], acc1[8];
#pragma unroll
    for (int p = 0; p < 8; p++) { acc0[p] = 0ull; acc1[p] = 0ull; }

    for (int kt = k0; kt < k1; kt += 128) {
        int kn = min(128, k1 - kt);
        __syncthreads();
#pragma unroll
        for (int idx = tid; idx < 2048; idx += 256) {
            int b = idx >> 7, kk = idx & 127;
            sf[kk][b] = (kk < kn) ? flat[(size_t)b * Kdim + kt + kk] : 0.0f;
        }
        __syncthreads();
        const float2* wrow = (const float2*)(Wp1 + (size_t)kt * NHID) + tid;
        for (int kk = 0; kk < kn; kk++) {
            float2 w = __ldcs(wrow);          // streaming: don't pollute L2
            wrow += 256;                       // next k row (512 floats)
            unsigned long long w0, w1;
            asm("mov.b64 %0, {%1, %2};" : "=l"(w0)
                : "r"(__float_as_uint(w.x)), "r"(__float_as_uint(w.x)));
            asm("mov.b64 %0, {%1, %2};" : "=l"(w1)
                : "r"(__float_as_uint(w.y)), "r"(__float_as_uint(w.y)));
#pragma unroll
            for (int p = 0; p < 8; p++) {
                unsigned long long fv =
                    *(const unsigned long long*)&sf[kk][2 * p];
                asm("fma.rn.f32x2 %0, %1, %2, %0;" : "+l"(acc0[p]) : "l"(w0), "l"(fv));
                asm("fma.rn.f32x2 %0, %1, %2, %0;" : "+l"(acc1[p]) : "l"(w1), "l"(fv));
            }
        }
    }
    int j = tid * 2;
#pragma unroll
    for (int p = 0; p < 8; p++) {
        float2 v0 = *(float2*)&acc0[p];   // col j:   (b=2p, b=2p+1)
        float2 v1 = *(float2*)&acc1[p];   // col j+1: (b=2p, b=2p+1)
        atomicAdd(&g_hid[(2 * p)     * NHID + j],     v0.x);
        atomicAdd(&g_hid[(2 * p + 1) * NHID + j],     v0.y);
        atomicAdd(&g_hid[(2 * p)     * NHID + j + 1], v1.x);
        atomicAdd(&g_hid[(2 * p + 1) * NHID + j + 1], v1.y);
    }
}

// ================= final: relu(hid+bp1) @ Wp2 + bp2 =================
__global__ void mlp2_k(const float* __restrict__ bp1, const float* __restrict__ Wp2,
                       const float* __restrict__ bp2, float* __restrict__ out)
{
    int t = threadIdx.x;
    int b = t >> 4, a = t & 15;
    float acc = bp2[a];
    for (int j = 0; j < NHID; j++) {
        float hv = fmaxf(g_hid[b * NHID + j] + bp1[j], 0.0f);
        acc = fmaf(hv, Wp2[j * NACT + a], acc);
    }
    out[b * NACT + a] = acc;
}

// ================= launch =================
extern "C" void kernel_launch(void* const* d_in, const int* in_sizes, int n_in,
                              void* d_out, int out_size)
{
    const float* features = (const float*)d_in[0];
    const void*  edge     = d_in[1];            // int32 or int64, detected on device
    const float* W1  = (const float*)d_in[2];
    const float* b1  = (const float*)d_in[3];
    const float* W2  = (const float*)d_in[4];
    const float* b2  = (const float*)d_in[5];
    const float* Wp1 = (const float*)d_in[6];
    const float* bp1 = (const float*)d_in[7];
    const float* Wp2 = (const float*)d_in[8];
    const float* bp2 = (const float*)d_in[9];
    float* out = (float*)d_out;

    float* bufA; cudaGetSymbolAddress((void**)&bufA, g_bufA);
    float* bufB; cudaGetSymbolAddress((void**)&bufB, g_bufB);

    // setup: dtype detect, degrees, dinv, CSR offsets, dst-sorted edge list
    detect_k<<<1, 32>>>((const unsigned int*)edge);
    init_k<<<(Bz * NHID + 255) / 256, 256>>>();
    hist_k<<<(Ee + 255) / 256, 256>>>(edge);
    scan_k<<<1, 1024>>>();
    scatter_k<<<(ETOT + 255) / 256, 256>>>(edge);

    // layer 1: xw = feat @ W1 ; h1 = relu(agg(xw) + b1)
    gemm_rows_k<<<(Bz * Nn) / 64, 256>>>(features, W1, bufA, Ff);
    agg_k<<<Nn, 512>>>(bufA, b1, bufB);

    // layer 2: xw2 = h1 @ W2 ; h2 = relu(agg(xw2) + b2)
    gemm_rows_k<<<(Bz * Nn) / 64, 256>>>(bufB, W2, bufA, Hh);
    agg_k<<<Nn, 512>>>(bufA, b2, bufB);

    // policy MLP
    mlp1_k<<<KSPLIT, 256>>>(bufB, Wp1);
    mlp2_k<<<1, 256>>>(bp1, Wp2, bp2, out);
}

// round 3
// speedup vs baseline: 1.0095x; 1.0095x over previous
#include <cuda_runtime.h>
#include <cuda_fp16.h>

// Problem constants
#define Bz 16
#define Nn 5000
#define Ff 64
#define Hh 32
#define Ee 160000
#define ETOT (Ee + Nn)         // edges + self loops = 165000
#define Kdim (Nn * Hh)         // 160000
#define NHID 512
#define NACT 16
#define KSPLIT 296

// -------- scratch (device globals; no allocation allowed) --------
__device__ int    g_is64;
__device__ int    g_deg[Nn];
__device__ int    g_cursor[Nn];
__device__ int    g_off[Nn + 1];
__device__ float  g_dinv[Nn];
__device__ int    g_srcs[ETOT];
__device__ float  g_nrms[ETOT];
__device__ __half g_xw1[Bz * Nn * Hh];   // 5.12 MB  (layer1 transformed feats, fp16)
__device__ __half g_xw2[Bz * Nn * Hh];   // 5.12 MB  (layer2 transformed feats, fp16)
__device__ float  g_h2[Bz * Nn * Hh];    // 10.24 MB (layer2 output, fp32 -> MLP input)
__device__ float  g_hid[Bz * NHID];      // MLP hidden partials

// edge index fetch that works for both int32 and int64 payloads
__device__ __forceinline__ int edge_at(const void* ei, int idx) {
    if (g_is64) return (int)((const long long*)ei)[idx];
    return ((const int*)ei)[idx];
}

// ================= setup =================

// init + dtype detect in one launch
__global__ void init_k(const unsigned int* __restrict__ ei) {
    int i = blockIdx.x * blockDim.x + threadIdx.x;
    if (i == 0) {
        int all0 = 1;
        for (int k = 0; k < 64; k++)
            if (ei[2 * k + 1] != 0u) { all0 = 0; break; }
        g_is64 = all0;
    }
    if (i < Nn) { g_deg[i] = 1; g_cursor[i] = 0; }   // deg starts at 1 (self loop)
    if (i < Bz * NHID) g_hid[i] = 0.0f;
}

__global__ void hist_k(const void* __restrict__ ei) {
    int e = blockIdx.x * blockDim.x + threadIdx.x;
    if (e < Ee) atomicAdd(&g_deg[edge_at(ei, Ee + e)], 1);
}

// single block: dinv + exclusive scan of degrees (warp-shuffle based)
__global__ void scan_k() {
    __shared__ int wsum[32];
    int t = threadIdx.x, lane = t & 31, wid = t >> 5;
    const int CH = 5;
    int base = t * CH;
    int d[CH];
    int local = 0;
#pragma unroll
    for (int j = 0; j < CH; j++) {
        int idx = base + j;
        d[j] = (idx < Nn) ? g_deg[idx] : 0;
        local += d[j];
    }
    // inclusive warp scan of local
    int incl = local;
#pragma unroll
    for (int off = 1; off < 32; off <<= 1) {
        int v = __shfl_up_sync(0xffffffffu, incl, off);
        if (lane >= off) incl += v;
    }
    if (lane == 31) wsum[wid] = incl;
    __syncthreads();
    if (wid == 0) {
        int v = wsum[lane];
        int iv = v;
#pragma unroll
        for (int off = 1; off < 32; off <<= 1) {
            int u = __shfl_up_sync(0xffffffffu, iv, off);
            if (lane >= off) iv += u;
        }
        wsum[lane] = iv;
    }
    __syncthreads();
    int excl = (wid ? wsum[wid - 1] : 0) + (incl - local);
#pragma unroll
    for (int j = 0; j < CH; j++) {
        int idx = base + j;
        if (idx < Nn) {
            g_off[idx] = excl;
            excl += d[j];
            g_dinv[idx] = rsqrtf((float)d[j]);
        }
    }
    if (t == 1023) g_off[Nn] = wsum[31];
}

__global__ void scatter_k(const void* __restrict__ ei) {
    int i = blockIdx.x * blockDim.x + threadIdx.x;
    if (i >= ETOT) return;
    int s, d;
    if (i < Ee) { s = edge_at(ei, i); d = edge_at(ei, Ee + i); }
    else        { s = d = i - Ee; }
    float nm = g_dinv[s] * g_dinv[d];
    int pos = g_off[d] + atomicAdd(&g_cursor[d], 1);
    g_srcs[pos] = s;
    g_nrms[pos] = nm;
}

// ================= layer1 GEMM: xw1[r,32] = feat[r,64] @ W1, fp16 out ==========
__global__ __launch_bounds__(256) void gemm1_k(
    const float* __restrict__ X, const float* __restrict__ W,
    __half* __restrict__ Y)
{
    const int F = Ff;
    __shared__ float sx[64 * Ff];
    __shared__ float sw[Ff * 32];
    int tid = threadIdx.x;
    for (int i = tid; i < F * 32; i += 256) sw[i] = W[i];
    long long r0 = (long long)blockIdx.x * 64;
    for (int i = tid; i < 64 * F; i += 256) {
        int r = i >> 6, c = i & 63;
        sx[r * F + c] = X[(r0 + r) * F + c];
    }
    __syncthreads();
    int h = tid & 31;
    int g = tid >> 5;               // 8 groups x 8 rows
    float acc[8] = {0.f, 0.f, 0.f, 0.f, 0.f, 0.f, 0.f, 0.f};
    for (int f = 0; f < F; f++) {
        float w = sw[f * 32 + h];
#pragma unroll
        for (int i = 0; i < 8; i++)
            acc[i] = fmaf(sx[(g * 8 + i) * F + f], w, acc[i]);
    }
#pragma unroll
    for (int i = 0; i < 8; i++)
        Y[(r0 + g * 8 + i) * 32 + h] = __float2half(acc[i]);
}

// ===== agg1 fused with layer2 transform:
//   h1 = relu(agg(xw1) + b1); xw2 = h1 @ W2   (per warp = one (node,batch) row)
__global__ __launch_bounds__(512) void agg1_fuse_k(
    const __half* __restrict__ xw, const float* __restrict__ b1,
    const float* __restrict__ W2, __half* __restrict__ out2)
{
    __shared__ float sW2[32 * 32];
    int tid = threadIdx.x;
    for (int i = tid; i < 1024; i += 512) sW2[i] = W2[i];
    __syncthreads();

    int n = blockIdx.x;
    int b = tid >> 5;
    int lane = tid & 31;
    int beg = g_off[n], end = g_off[n + 1];
    const __half* xb = xw + (size_t)b * (Nn * Hh);
    float a0 = 0.f, a1 = 0.f, a2 = 0.f, a3 = 0.f;
    int e = beg;
    for (; e + 4 <= end; e += 4) {
        int s0 = g_srcs[e], s1 = g_srcs[e + 1], s2 = g_srcs[e + 2], s3 = g_srcs[e + 3];
        float m0 = g_nrms[e], m1 = g_nrms[e + 1], m2 = g_nrms[e + 2], m3 = g_nrms[e + 3];
        a0 = fmaf(m0, __half2float(xb[s0 * 32 + lane]), a0);
        a1 = fmaf(m1, __half2float(xb[s1 * 32 + lane]), a1);
        a2 = fmaf(m2, __half2float(xb[s2 * 32 + lane]), a2);
        a3 = fmaf(m3, __half2float(xb[s3 * 32 + lane]), a3);
    }
    for (; e < end; e++)
        a0 = fmaf(g_nrms[e], __half2float(xb[g_srcs[e] * 32 + lane]), a0);
    float h = fmaxf((a0 + a1) + (a2 + a3) + b1[lane], 0.0f);

    // xw2 row = h1row @ W2 via lane broadcast
    float o = 0.f;
#pragma unroll
    for (int f = 0; f < 32; f++) {
        float hf = __shfl_sync(0xffffffffu, h, f);
        o = fmaf(hf, sW2[f * 32 + lane], o);
    }
    out2[((size_t)b * Nn + n) * 32 + lane] = __float2half(o);
}

// ===== agg2: h2 = relu(agg(xw2) + b2), fp32 out =====
__global__ __launch_bounds__(512) void agg2_k(
    const __half* __restrict__ xw, const float* __restrict__ bias,
    float* __restrict__ out)
{
    int n = blockIdx.x;
    int b = threadIdx.x >> 5;
    int lane = threadIdx.x & 31;
    int beg = g_off[n], end = g_off[n + 1];
    const __half* xb = xw + (size_t)b * (Nn * Hh);
    float a0 = 0.f, a1 = 0.f, a2 = 0.f, a3 = 0.f;
    int e = beg;
    for (; e + 4 <= end; e += 4) {
        int s0 = g_srcs[e], s1 = g_srcs[e + 1], s2 = g_srcs[e + 2], s3 = g_srcs[e + 3];
        float m0 = g_nrms[e], m1 = g_nrms[e + 1], m2 = g_nrms[e + 2], m3 = g_nrms[e + 3];
        a0 = fmaf(m0, __half2float(xb[s0 * 32 + lane]), a0);
        a1 = fmaf(m1, __half2float(xb[s1 * 32 + lane]), a1);
        a2 = fmaf(m2, __half2float(xb[s2 * 32 + lane]), a2);
        a3 = fmaf(m3, __half2float(xb[s3 * 32 + lane]), a3);
    }
    for (; e < end; e++)
        a0 = fmaf(g_nrms[e], __half2float(xb[g_srcs[e] * 32 + lane]), a0);
    float r = (a0 + a1) + (a2 + a3) + bias[lane];
    out[((size_t)b * Nn + n) * 32 + lane] = fmaxf(r, 0.0f);
}

// ===== big MLP GEMM: split-K, f32x2; thread = 4 cols x 8 batches =====
__global__ __launch_bounds__(256) void mlp1_k(
    const float* __restrict__ flat, const float* __restrict__ Wp1)
{
    __shared__ __align__(16) float sf[128][20];   // [k-within-tile][batch], 80B rows
    int tid = threadIdx.x;
    int half = tid >> 7;                 // batch group: 8*half .. 8*half+7
    int c4 = (tid & 127) * 4;            // columns c4 .. c4+3
    const int chunk = (Kdim + KSPLIT - 1) / KSPLIT;   // 541
    int k0 = blockIdx.x * chunk;
    int k1 = min(k0 + chunk, Kdim);

    unsigned long long acc[4][4];
#pragma unroll
    for (int i = 0; i < 4; i++)
#pragma unroll
        for (int p = 0; p < 4; p++) acc[i][p] = 0ull;

    for (int kt = k0; kt < k1; kt += 128) {
        int kn = min(128, k1 - kt);
        __syncthreads();
#pragma unroll
        for (int idx = tid; idx < 2048; idx += 256) {
            int b = idx >> 7, kk = idx & 127;
            sf[kk][b] = (kk < kn) ? flat[(size_t)b * Kdim + kt + kk] : 0.0f;
        }
        __syncthreads();
        const float4* wp = (const float4*)(Wp1 + (size_t)kt * NHID + c4);
        for (int kk = 0; kk < kn; kk++) {
            float4 w = __ldcs(wp);
            wp += NHID / 4;
            unsigned long long wd[4];
            asm("mov.b64 %0, {%1, %1};" : "=l"(wd[0]) : "r"(__float_as_uint(w.x)));
            asm("mov.b64 %0, {%1, %1};" : "=l"(wd[1]) : "r"(__float_as_uint(w.y)));
            asm("mov.b64 %0, {%1, %1};" : "=l"(wd[2]) : "r"(__float_as_uint(w.z)));
            asm("mov.b64 %0, {%1, %1};" : "=l"(wd[3]) : "r"(__float_as_uint(w.w)));
            const float4* fv4 = (const float4*)&sf[kk][half * 8];
            float4 f0 = fv4[0], f1 = fv4[1];
            unsigned long long fp[4];
            asm("mov.b64 %0, {%1, %2};" : "=l"(fp[0])
                : "r"(__float_as_uint(f0.x)), "r"(__float_as_uint(f0.y)));
            asm("mov.b64 %0, {%1, %2};" : "=l"(fp[1])
                : "r"(__float_as_uint(f0.z)), "r"(__float_as_uint(f0.w)));
            asm("mov.b64 %0, {%1, %2};" : "=l"(fp[2])
                : "r"(__float_as_uint(f1.x)), "r"(__float_as_uint(f1.y)));
            asm("mov.b64 %0, {%1, %2};" : "=l"(fp[3])
                : "r"(__float_as_uint(f1.z)), "r"(__float_as_uint(f1.w)));
#pragma unroll
            for (int i = 0; i < 4; i++)
#pragma unroll
                for (int p = 0; p < 4; p++)
                    asm("fma.rn.f32x2 %0, %1, %2, %0;"
                        : "+l"(acc[i][p]) : "l"(wd[i]), "l"(fp[p]));
        }
    }
#pragma unroll
    for (int i = 0; i < 4; i++)
#pragma unroll
        for (int p = 0; p < 4; p++) {
            float2 v = *(float2*)&acc[i][p];   // batches (8*half+2p, +1), col c4+i
            atomicAdd(&g_hid[(half * 8 + 2 * p)     * NHID + c4 + i], v.x);
            atomicAdd(&g_hid[(half * 8 + 2 * p + 1) * NHID + c4 + i], v.y);
        }
}

// ===== final: relu(hid+bp1) @ Wp2 + bp2, one block per batch =====
__global__ __launch_bounds__(512) void mlp2_k(
    const float* __restrict__ bp1, const float* __restrict__ Wp2,
    const float* __restrict__ bp2, float* __restrict__ out)
{
    __shared__ float part[16][NACT];
    int b = blockIdx.x;
    int j = threadIdx.x;
    int wid = j >> 5, lane = j & 31;
    float hv = fmaxf(g_hid[b * NHID + j] + bp1[j], 0.0f);
    float acc[NACT];
#pragma unroll
    for (int a = 0; a < NACT; a++) acc[a] = hv * Wp2[j * NACT + a];
#pragma unroll
    for (int off = 16; off; off >>= 1)
#pragma unroll
        for (int a = 0; a < NACT; a++)
            acc[a] += __shfl_down_sync(0xffffffffu, acc[a], off);
    if (lane == 0)
#pragma unroll
        for (int a = 0; a < NACT; a++) part[wid][a] = acc[a];
    __syncthreads();
    if (j < NACT) {
        float s = bp2[j];
#pragma unroll
        for (int w = 0; w < 16; w++) s += part[w][j];
        out[b * NACT + j] = s;
    }
}

// ================= launch =================
extern "C" void kernel_launch(void* const* d_in, const int* in_sizes, int n_in,
                              void* d_out, int out_size)
{
    const float* features = (const float*)d_in[0];
    const void*  edge     = d_in[1];            // int32 or int64, detected on device
    const float* W1  = (const float*)d_in[2];
    const float* b1  = (const float*)d_in[3];
    const float* W2  = (const float*)d_in[4];
    const float* b2  = (const float*)d_in[5];
    const float* Wp1 = (const float*)d_in[6];
    const float* bp1 = (const float*)d_in[7];
    const float* Wp2 = (const float*)d_in[8];
    const float* bp2 = (const float*)d_in[9];
    float* out = (float*)d_out;

    __half* xw1; cudaGetSymbolAddress((void**)&xw1, g_xw1);
    __half* xw2; cudaGetSymbolAddress((void**)&xw2, g_xw2);
    float*  h2;  cudaGetSymbolAddress((void**)&h2,  g_h2);

    // setup: dtype detect + init, degrees, scan, dst-sorted edge list
    init_k<<<(Bz * NHID + 255) / 256, 256>>>((const unsigned int*)edge);
    hist_k<<<(Ee + 255) / 256, 256>>>(edge);
    scan_k<<<1, 1024>>>();
    scatter_k<<<(ETOT + 255) / 256, 256>>>(edge);

    // layer 1 transform; fused (agg1 + relu + layer2 transform); agg2
    gemm1_k<<<(Bz * Nn) / 64, 256>>>(features, W1, xw1);
    agg1_fuse_k<<<Nn, 512>>>(xw1, b1, W2, xw2);
    agg2_k<<<Nn, 512>>>(xw2, b2, h2);

    // policy MLP
    mlp1_k<<<KSPLIT, 256>>>(h2, Wp1);
    mlp2_k<<<Bz, 512>>>(bp1, Wp2, bp2, out);
}